// round 13
// baseline (speedup 1.0000x reference)
#include <cuda_runtime.h>
#include <cuda_bf16.h>
#include <cstdint>

// ============================================================================
// Fused flash attention (HMMA, base sm_103 target), concurrent 2-branch graph:
//   branch A (forked stream): persistent mask_kernel — 148 CTAs x 128 thr
//       (1 warp/SMSP) computing all threefry keep-words it-major with
//       per-(cta,it) release flags. Low residency so it fills ONLY the issue
//       slots the attention kernel leaves idle.
//   branch B (main stream): split_kernel -> attn_hmma_kernel (acquire-spin
//       on the flag before consuming each iter's mask).
// Dropout = JAX partitionable threefry2x32, key (0,42), bits=o1^o2,
// keep <=> bits < 7549747*512  (bit-exact, verified round 2).
// ============================================================================

namespace cfg {
constexpr int H = 128, SEQ = 4096, BQ = 128, BK = 64;
constexpr int NIT = SEQ / BK;                      // 64
constexpr int THREADS = 256;
constexpr uint32_t KEEP = 3865470464u;
constexpr float SCALE = 11.313708498984760390f * 1.4426950408889634074f; // sqrt(128)*log2e
constexpr int RS     = 272;
constexpr int QTILE  = BQ * RS;
constexpr int KTILE  = BK * RS;
constexpr int SM_QHI = 0;
constexpr int SM_QLO = QTILE;
constexpr int SM_BUF0 = 2 * QTILE;
constexpr int BUFSZ  = 4 * KTILE;
constexpr int SMEM_TOTAL = SM_BUF0 + 2 * BUFSZ;    // 208896 B
constexpr int MASK_CTAS = 148;
constexpr int NWORK = 128 * NIT;                   // 8192 items (c x it)
}

// ---- device globals --------------------------------------------------------
__device__ __align__(16) uint32_t g_Qhi[1048576];
__device__ __align__(16) uint32_t g_Qlo[1048576];
__device__ __align__(16) uint32_t g_Khi[1048576];
__device__ __align__(16) uint32_t g_Klo[1048576];
__device__ __align__(16) uint32_t g_Vhi[1048576];
__device__ __align__(16) uint32_t g_Vlo[1048576];
__device__ __align__(16) uint32_t g_mask[2097152];  // keep-words
__device__ uint32_t g_flags[8192];                  // per (cta,it) ready flags

// ---------------------------------------------------------------------------
// 8-way interleaved threefry-2x32-20, key (0,42), ctr (0,m) -> o1^o2
#define TFR8(r) \
    _Pragma("unroll") \
    for (int j = 0; j < 8; ++j) { \
        a[j] += b[j]; b[j] = __funnelshift_l(b[j], b[j], (r)); b[j] ^= a[j]; }
#define TFI8(ka, kb) \
    _Pragma("unroll") \
    for (int j = 0; j < 8; ++j) { a[j] += (ka); b[j] += (kb); }

__device__ __forceinline__ void tf8(const uint32_t* ctr, uint32_t* out) {
    const uint32_t K1 = 42u, K2 = 0x1BD11BF0u;
    uint32_t a[8], b[8];
    #pragma unroll
    for (int j = 0; j < 8; ++j) { a[j] = 0u; b[j] = ctr[j] + K1; }
    TFR8(13) TFR8(15) TFR8(26) TFR8(6)
    TFI8(K1, K2 + 1u)
    TFR8(17) TFR8(29) TFR8(16) TFR8(24)
    TFI8(K2, 2u)
    TFR8(13) TFR8(15) TFR8(26) TFR8(6)
    TFI8(0u, K1 + 3u)
    TFR8(17) TFR8(29) TFR8(16) TFR8(24)
    TFI8(K1, K2 + 4u)
    TFR8(13) TFR8(15) TFR8(26) TFR8(6)
    TFI8(K2, 5u)
    #pragma unroll
    for (int j = 0; j < 8; ++j) out[j] = a[j] ^ b[j];
}

// ---------------------------------------------------------------------------
__device__ __forceinline__ uint32_t smem_u32(const void* p) {
    uint32_t a;
    asm("{ .reg .u64 t; cvta.to.shared.u64 t, %1; cvt.u32.u64 %0, t; }" : "=r"(a) : "l"(p));
    return a;
}
__device__ __forceinline__ void cpa16(uint32_t dst, const void* src) {
    asm volatile("cp.async.cg.shared.global [%0], [%1], 16;" :: "r"(dst), "l"(src) : "memory");
}
__device__ __forceinline__ void cpa_commit() {
    asm volatile("cp.async.commit_group;" ::: "memory");
}
__device__ __forceinline__ void cpa_wait0() {
    asm volatile("cp.async.wait_group 0;" ::: "memory");
}
__device__ __forceinline__ void ldsm4(uint32_t* r, uint32_t addr) {
    asm volatile("ldmatrix.sync.aligned.m8n8.x4.shared.b16 {%0,%1,%2,%3}, [%4];"
                 : "=r"(r[0]), "=r"(r[1]), "=r"(r[2]), "=r"(r[3]) : "r"(addr));
}
__device__ __forceinline__ void ldsm4t(uint32_t* r, uint32_t addr) {
    asm volatile("ldmatrix.sync.aligned.m8n8.x4.trans.shared.b16 {%0,%1,%2,%3}, [%4];"
                 : "=r"(r[0]), "=r"(r[1]), "=r"(r[2]), "=r"(r[3]) : "r"(addr));
}
__device__ __forceinline__ void mma16816(float* d, const uint32_t* a, uint32_t b0, uint32_t b1) {
    asm volatile("mma.sync.aligned.m16n8k16.row.col.f32.bf16.bf16.f32 "
                 "{%0,%1,%2,%3}, {%4,%5,%6,%7}, {%8,%9}, {%0,%1,%2,%3};"
                 : "+f"(d[0]), "+f"(d[1]), "+f"(d[2]), "+f"(d[3])
                 : "r"(a[0]), "r"(a[1]), "r"(a[2]), "r"(a[3]), "r"(b0), "r"(b1));
}
__device__ __forceinline__ float ex2f(float x) {
    float r; asm("ex2.approx.f32 %0, %1;" : "=f"(r) : "f"(x)); return r;
}
__device__ __forceinline__ void split2f(float x, float y, uint32_t& hi, uint32_t& lo) {
    uint32_t h;
    asm("cvt.rn.bf16x2.f32 %0, %1, %2;" : "=r"(h) : "f"(y), "f"(x));
    float fx = __uint_as_float(h << 16);
    float fy = __uint_as_float(h & 0xffff0000u);
    uint32_t l;
    asm("cvt.rn.bf16x2.f32 %0, %1, %2;" : "=r"(l) : "f"(y - fy), "f"(x - fx));
    hi = h; lo = l;
}

// ============================================================================
// Kernel 1: split Q/K/V into bf16 hi/lo (Q pre-scaled)
// ============================================================================
__global__ __launch_bounds__(256)
void split_kernel(const float* __restrict__ Q,
                  const float* __restrict__ K,
                  const float* __restrict__ V) {
    using namespace cfg;
    const int i0 = blockIdx.x * 256 + threadIdx.x;
    #pragma unroll
    for (int r = 0; r < 2; ++r) {
        int i = i0 + r * 262144;
        float4 v = ((const float4*)Q)[i];
        v.x *= SCALE; v.y *= SCALE; v.z *= SCALE; v.w *= SCALE;
        uint32_t h0, l0, h1, l1;
        split2f(v.x, v.y, h0, l0); split2f(v.z, v.w, h1, l1);
        ((uint2*)g_Qhi)[i] = make_uint2(h0, h1);
        ((uint2*)g_Qlo)[i] = make_uint2(l0, l1);

        v = ((const float4*)K)[i];
        split2f(v.x, v.y, h0, l0); split2f(v.z, v.w, h1, l1);
        ((uint2*)g_Khi)[i] = make_uint2(h0, h1);
        ((uint2*)g_Klo)[i] = make_uint2(l0, l1);

        v = ((const float4*)V)[i];
        split2f(v.x, v.y, h0, l0); split2f(v.z, v.w, h1, l1);
        ((uint2*)g_Vhi)[i] = make_uint2(h0, h1);
        ((uint2*)g_Vlo)[i] = make_uint2(l0, l1);
    }
}

// ============================================================================
// Kernel 2: PERSISTENT mask kernel — 148 CTAs x 128 threads (1 warp/SMSP).
//   Work item w (it-major): it = w>>7, c = w&127; 256 keep-words per item
//   (each thread computes 2). Word content/index bit-identical to round 10.
// ============================================================================
__global__ __launch_bounds__(128)
void mask_kernel() {
    using namespace cfg;
    const int tid = threadIdx.x;
    for (int w = blockIdx.x; w < NWORK; w += MASK_CTAS) {
        const int it = w >> 7;
        const int c  = w & 127;
        const int bb = c >> 5, qt = c & 31;
        const int vb = it * BK;
        #pragma unroll
        for (int half = 0; half < 2; ++half) {
            const int t = tid + half * 128;
            const int wd = t >> 5, lane = t & 31;
            const int qrow = qt * BQ + wd * 16 + (lane >> 2);
            const uint32_t mrow0 = ((uint32_t)bb << 24) | ((uint32_t)qrow << 12);
            const uint32_t mrow1 = mrow0 + (8u << 12);
            uint32_t keep = 0u;
            #pragma unroll
            for (int ks = 0; ks < 4; ++ks) {
                uint32_t ctr[8], bits[8];
                #pragma unroll
                for (int h2 = 0; h2 < 2; ++h2) {
                    uint32_t cc = (uint32_t)(vb + (2 * ks + h2) * 8 + (lane & 3) * 2);
                    ctr[h2 * 4 + 0] = mrow0 + cc;
                    ctr[h2 * 4 + 1] = mrow0 + cc + 1u;
                    ctr[h2 * 4 + 2] = mrow1 + cc;
                    ctr[h2 * 4 + 3] = mrow1 + cc + 1u;
                }
                tf8(ctr, bits);
                #pragma unroll
                for (int u = 0; u < 8; ++u)
                    if (bits[u] < KEEP) keep |= 1u << (ks * 8 + u);
            }
            g_mask[(uint32_t)(c * 64 + it) * 256u + (uint32_t)t] = keep;
        }
        __syncthreads();
        if (tid == 0) {
            __threadfence();
            atomicExch(&g_flags[c * 64 + it], 1u);
        }
    }
}

// ============================================================================
// Kernel 3: flash attention (HMMA); spins on the per-iter mask flag.
// ============================================================================
__global__ __launch_bounds__(cfg::THREADS, 1)
void attn_hmma_kernel(float* __restrict__ Og) {
    using namespace cfg;
    extern __shared__ char smem[];
    const uint32_t sb = smem_u32(smem);

    const int tid  = threadIdx.x;
    const int wid  = tid >> 5;
    const int lane = tid & 31;
    const int qt   = blockIdx.x;
    const int qblk = qt * BQ;
    const int bb   = blockIdx.y;
    const int cidx = bb * 32 + qt;

    const size_t tbase = (size_t)bb * SEQ * H;

    // ---- prologue: cp.async Q tile (hi+lo) and K/V tile 0 ----
    {
        const char* qh = (const char*)g_Qhi + (tbase + (size_t)qblk * H) * 2;
        const char* ql = (const char*)g_Qlo + (tbase + (size_t)qblk * H) * 2;
        #pragma unroll
        for (int i = 0; i < 8; ++i) {
            int idx = tid + i * 256;
            int row = idx >> 4, c = idx & 15;
            cpa16(sb + SM_QHI + row * RS + c * 16, qh + row * 256 + c * 16);
            cpa16(sb + SM_QLO + row * RS + c * 16, ql + row * 256 + c * 16);
        }
        const char* kh = (const char*)g_Khi + tbase * 2;
        const char* kl = (const char*)g_Klo + tbase * 2;
        const char* vh = (const char*)g_Vhi + tbase * 2;
        const char* vl = (const char*)g_Vlo + tbase * 2;
        #pragma unroll
        for (int j = 0; j < 4; ++j) {
            int idx = tid + j * 256;
            int row = idx >> 4, c = idx & 15;
            uint32_t d = sb + SM_BUF0 + row * RS + c * 16;
            int      s = row * 256 + c * 16;
            cpa16(d,             kh + s);
            cpa16(d + KTILE,     kl + s);
            cpa16(d + 2 * KTILE, vh + s);
            cpa16(d + 3 * KTILE, vl + s);
        }
        cpa_commit();
        cpa_wait0();
    }
    __syncthreads();

    const uint32_t abase   = sb + SM_QHI + (wid * 16 + (lane & 15)) * RS + (lane >> 4) * 16;
    const uint32_t kb_lane = (lane & 15) * RS + (lane >> 4) * 16;

    float o[16][4];
    #pragma unroll
    for (int j = 0; j < 16; ++j)
        #pragma unroll
        for (int c = 0; c < 4; ++c) o[j][c] = 0.0f;
    float m0 = -1e30f, m1 = -1e30f, l0 = 0.0f, l1 = 0.0f;

    for (int it = 0; it < NIT; ++it) {
        // ---- cp.async K/V tile it+1 into the other buffer ----
        if (it + 1 < NIT) {
            const size_t vb2 = (size_t)(it + 1) * BK;
            uint32_t bufn = sb + SM_BUF0 + (uint32_t)(((it + 1) & 1) * BUFSZ);
            const char* kh = (const char*)g_Khi + (tbase + vb2 * H) * 2;
            const char* kl = (const char*)g_Klo + (tbase + vb2 * H) * 2;
            const char* vh = (const char*)g_Vhi + (tbase + vb2 * H) * 2;
            const char* vl = (const char*)g_Vlo + (tbase + vb2 * H) * 2;
            #pragma unroll
            for (int j = 0; j < 4; ++j) {
                int idx = tid + j * 256;
                int row = idx >> 4, c = idx & 15;
                uint32_t d = bufn + row * RS + c * 16;
                int      s = row * 256 + c * 16;
                cpa16(d,             kh + s);
                cpa16(d + KTILE,     kl + s);
                cpa16(d + 2 * KTILE, vh + s);
                cpa16(d + 3 * KTILE, vl + s);
            }
            cpa_commit();
        }

        const uint32_t bufc = sb + SM_BUF0 + (uint32_t)((it & 1) * BUFSZ);
        const uint32_t bK = bufc + kb_lane;
        const uint32_t bV = bufc + 2 * KTILE + kb_lane;

        // ---- S = Qh*Kh + Qh*Kl + Ql*Kh ----
        float s[8][4];
        #pragma unroll
        for (int j = 0; j < 8; ++j)
            #pragma unroll
            for (int c = 0; c < 4; ++c) s[j][c] = 0.0f;

        #pragma unroll
        for (int ks = 0; ks < 8; ++ks) {
            uint32_t ah[4], al[4];
            ldsm4(ah, abase + ks * 32);
            ldsm4(al, abase + QTILE + ks * 32);
            #pragma unroll
            for (int np = 0; np < 2; ++np) {
                uint32_t bh0[4], bl0[4], bh1[4], bl1[4];
                ldsm4(bh0, bK + (2 * np) * (16 * RS) + ks * 32);
                ldsm4(bl0, bK + KTILE + (2 * np) * (16 * RS) + ks * 32);
                ldsm4(bh1, bK + (2 * np + 1) * (16 * RS) + ks * 32);
                ldsm4(bl1, bK + KTILE + (2 * np + 1) * (16 * RS) + ks * 32);
                float* s0 = s[4 * np];     float* s1 = s[4 * np + 1];
                float* s2 = s[4 * np + 2]; float* s3 = s[4 * np + 3];
                mma16816(s0, ah, bh0[0], bh0[2]);
                mma16816(s1, ah, bh0[1], bh0[3]);
                mma16816(s2, ah, bh1[0], bh1[2]);
                mma16816(s3, ah, bh1[1], bh1[3]);
                mma16816(s0, ah, bl0[0], bl0[2]);
                mma16816(s1, ah, bl0[1], bl0[3]);
                mma16816(s2, ah, bl1[0], bl1[2]);
                mma16816(s3, ah, bl1[1], bl1[3]);
                mma16816(s0, al, bh0[0], bh0[2]);
                mma16816(s1, al, bh0[1], bh0[3]);
                mma16816(s2, al, bh1[0], bh1[2]);
                mma16816(s3, al, bh1[1], bh1[3]);
            }
        }

        // ---- online softmax (log2 units) ----
        float mx0 = -1e30f, mx1 = -1e30f;
        #pragma unroll
        for (int j = 0; j < 8; ++j) {
            mx0 = fmaxf(mx0, fmaxf(s[j][0], s[j][1]));
            mx1 = fmaxf(mx1, fmaxf(s[j][2], s[j][3]));
        }
        #pragma unroll
        for (int off = 1; off < 4; off <<= 1) {
            mx0 = fmaxf(mx0, __shfl_xor_sync(0xffffffffu, mx0, off));
            mx1 = fmaxf(mx1, __shfl_xor_sync(0xffffffffu, mx1, off));
        }
        float mn0 = fmaxf(m0, mx0), mn1 = fmaxf(m1, mx1);
        float al0 = ex2f(m0 - mn0), al1 = ex2f(m1 - mn1);
        m0 = mn0; m1 = mn1;

        float ls0 = 0.0f, ls1 = 0.0f;
        #pragma unroll
        for (int j = 0; j < 8; ++j) {
            s[j][0] = ex2f(s[j][0] - mn0); ls0 += s[j][0];
            s[j][1] = ex2f(s[j][1] - mn0); ls0 += s[j][1];
            s[j][2] = ex2f(s[j][2] - mn1); ls1 += s[j][2];
            s[j][3] = ex2f(s[j][3] - mn1); ls1 += s[j][3];
        }
        #pragma unroll
        for (int off = 1; off < 4; off <<= 1) {
            ls0 += __shfl_xor_sync(0xffffffffu, ls0, off);
            ls1 += __shfl_xor_sync(0xffffffffu, ls1, off);
        }
        l0 = l0 * al0 + ls0;
        l1 = l1 * al1 + ls1;

        #pragma unroll
        for (int j = 0; j < 16; ++j) {
            o[j][0] *= al0; o[j][1] *= al0;
            o[j][2] *= al1; o[j][3] *= al1;
        }

        // ---- wait for this iter's mask flag, then load keep word ----
        {
            uint32_t f;
            const uint32_t* fp = &g_flags[cidx * 64 + it];
            do {
                asm volatile("ld.global.acquire.gpu.b32 %0, [%1];" : "=r"(f) : "l"(fp));
                if (!f) __nanosleep(128);
            } while (!f);
        }
        const uint32_t keep = g_mask[(uint32_t)(cidx * 64 + it) * 256u + (uint32_t)tid];

        // ---- apply keep bits + build P hi/lo fragments + PV MMAs ----
        #pragma unroll
        for (int ks = 0; ks < 4; ++ks) {
            uint32_t phi4[4], plo4[4];
            #pragma unroll
            for (int h2 = 0; h2 < 2; ++h2) {
                int j = 2 * ks + h2;
                uint32_t kb = keep >> (ks * 8 + h2 * 4);
                float p0 = (kb & 1u) ? s[j][0] : 0.0f;
                float p1 = (kb & 2u) ? s[j][1] : 0.0f;
                float p2 = (kb & 4u) ? s[j][2] : 0.0f;
                float p3 = (kb & 8u) ? s[j][3] : 0.0f;
                split2f(p0, p1, phi4[h2 * 2],     plo4[h2 * 2]);
                split2f(p2, p3, phi4[h2 * 2 + 1], plo4[h2 * 2 + 1]);
            }
            #pragma unroll
            for (int hp = 0; hp < 4; ++hp) {
                uint32_t bh0[4], bl0[4], bh1[4], bl1[4];
                ldsm4t(bh0, bV + ks * (16 * RS) + (2 * hp) * 32);
                ldsm4t(bl0, bV + KTILE + ks * (16 * RS) + (2 * hp) * 32);
                ldsm4t(bh1, bV + ks * (16 * RS) + (2 * hp + 1) * 32);
                ldsm4t(bl1, bV + KTILE + ks * (16 * RS) + (2 * hp + 1) * 32);
                float* o0 = o[4 * hp];     float* o1 = o[4 * hp + 1];
                float* o2 = o[4 * hp + 2]; float* o3 = o[4 * hp + 3];
                mma16816(o0, phi4, bh0[0], bh0[1]);
                mma16816(o1, phi4, bh0[2], bh0[3]);
                mma16816(o2, phi4, bh1[0], bh1[1]);
                mma16816(o3, phi4, bh1[2], bh1[3]);
                mma16816(o0, phi4, bl0[0], bl0[1]);
                mma16816(o1, phi4, bl0[2], bl0[3]);
                mma16816(o2, phi4, bl1[0], bl1[1]);
                mma16816(o3, phi4, bl1[2], bl1[3]);
                mma16816(o0, plo4, bh0[0], bh0[1]);
                mma16816(o1, plo4, bh0[2], bh0[3]);
                mma16816(o2, plo4, bh1[0], bh1[1]);
                mma16816(o3, plo4, bh1[2], bh1[3]);
            }
        }

        cpa_wait0();
        __syncthreads();
    }

    // ---- epilogue: O /= (0.9 * l) ----
    const int row_g0 = qblk + wid * 16 + (lane >> 2);
    float inv0 = 1.0f / (0.9f * l0);
    float inv1 = 1.0f / (0.9f * l1);
    float* out0 = Og + ((size_t)bb * SEQ + row_g0) * H;
    float* out1 = out0 + 8 * H;
    #pragma unroll
    for (int j = 0; j < 16; ++j) {
        int h = j * 8 + (lane & 3) * 2;
        *(float2*)(out0 + h) = make_float2(o[j][0] * inv0, o[j][1] * inv0);
        *(float2*)(out1 + h) = make_float2(o[j][2] * inv1, o[j][3] * inv1);
    }
}

// ============================================================================
extern "C" void kernel_launch(void* const* d_in, const int* in_sizes, int n_in,
                              void* d_out, int out_size) {
    const float* Q = (const float*)d_in[0];
    const float* K = (const float*)d_in[1];
    const float* V = (const float*)d_in[2];
    float* O = (float*)d_out;
    (void)in_sizes; (void)n_in; (void)out_size;

    static cudaStream_t s2 = nullptr;
    static cudaEvent_t evF = nullptr, evJ = nullptr;
    if (s2 == nullptr) {
        cudaStreamCreateWithFlags(&s2, cudaStreamNonBlocking);
        cudaEventCreateWithFlags(&evF, cudaEventDisableTiming);
        cudaEventCreateWithFlags(&evJ, cudaEventDisableTiming);
        cudaFuncSetAttribute(attn_hmma_kernel,
                             cudaFuncAttributeMaxDynamicSharedMemorySize,
                             cfg::SMEM_TOTAL);
    }

    // fork: persistent low-residency mask kernel runs beside split->attn
    cudaEventRecord(evF, 0);
    cudaStreamWaitEvent(s2, evF, 0);
    mask_kernel<<<cfg::MASK_CTAS, 128, 0, s2>>>();

    split_kernel<<<1024, 256>>>(Q, K, V);
    dim3 grid(cfg::SEQ / cfg::BQ, 4);
    attn_hmma_kernel<<<grid, cfg::THREADS, cfg::SMEM_TOTAL>>>(O);

    // join
    cudaEventRecord(evJ, s2);
    cudaStreamWaitEvent(0, evJ, 0);
}

// round 14
// speedup vs baseline: 1.2515x; 1.2515x over previous
#include <cuda_runtime.h>
#include <cuda_bf16.h>
#include <cstdint>

// ============================================================================
// Fused flash attention (HMMA, base sm_103 target), concurrent 2-branch graph:
//   branch A (forked stream): persistent mask_kernel — 128 CTAs x 256 thr.
//       CTA k owns mask column c=k and produces (c, it) for it=0..63 in
//       consumption order, releasing a flag per item. Grid <= SM count so it
//       can never flood; 256thr x ~31regs co-resides beside the attn CTA.
//   branch B (main stream): split_kernel -> attn_hmma_kernel (acquire-spin on
//       the flag just before softmax; mask word load hides under softmax).
// Dropout = JAX partitionable threefry2x32, key (0,42), bits=o1^o2,
// keep <=> bits < 7549747*512  (bit-exact, verified round 2).
// ============================================================================

namespace cfg {
constexpr int H = 128, SEQ = 4096, BQ = 128, BK = 64;
constexpr int NIT = SEQ / BK;                      // 64
constexpr int THREADS = 256;
constexpr uint32_t KEEP = 3865470464u;
constexpr float SCALE = 11.313708498984760390f * 1.4426950408889634074f; // sqrt(128)*log2e
constexpr int RS     = 272;
constexpr int QTILE  = BQ * RS;
constexpr int KTILE  = BK * RS;
constexpr int SM_QHI = 0;
constexpr int SM_QLO = QTILE;
constexpr int SM_BUF0 = 2 * QTILE;
constexpr int BUFSZ  = 4 * KTILE;
constexpr int SMEM_TOTAL = SM_BUF0 + 2 * BUFSZ;    // 208896 B
constexpr int MASK_CTAS = 128;                     // == attn CTA count
}

// ---- device globals --------------------------------------------------------
__device__ __align__(16) uint32_t g_Qhi[1048576];
__device__ __align__(16) uint32_t g_Qlo[1048576];
__device__ __align__(16) uint32_t g_Khi[1048576];
__device__ __align__(16) uint32_t g_Klo[1048576];
__device__ __align__(16) uint32_t g_Vhi[1048576];
__device__ __align__(16) uint32_t g_Vlo[1048576];
__device__ __align__(16) uint32_t g_mask[2097152];  // keep-words
__device__ uint32_t g_flags[8192];                  // per (cta,it) ready flags

// ---------------------------------------------------------------------------
// 8-way interleaved threefry-2x32-20, key (0,42), ctr (0,m) -> o1^o2
#define TFR8(r) \
    _Pragma("unroll") \
    for (int j = 0; j < 8; ++j) { \
        a[j] += b[j]; b[j] = __funnelshift_l(b[j], b[j], (r)); b[j] ^= a[j]; }
#define TFI8(ka, kb) \
    _Pragma("unroll") \
    for (int j = 0; j < 8; ++j) { a[j] += (ka); b[j] += (kb); }

__device__ __forceinline__ void tf8(const uint32_t* ctr, uint32_t* out) {
    const uint32_t K1 = 42u, K2 = 0x1BD11BF0u;
    uint32_t a[8], b[8];
    #pragma unroll
    for (int j = 0; j < 8; ++j) { a[j] = 0u; b[j] = ctr[j] + K1; }
    TFR8(13) TFR8(15) TFR8(26) TFR8(6)
    TFI8(K1, K2 + 1u)
    TFR8(17) TFR8(29) TFR8(16) TFR8(24)
    TFI8(K2, 2u)
    TFR8(13) TFR8(15) TFR8(26) TFR8(6)
    TFI8(0u, K1 + 3u)
    TFR8(17) TFR8(29) TFR8(16) TFR8(24)
    TFI8(K1, K2 + 4u)
    TFR8(13) TFR8(15) TFR8(26) TFR8(6)
    TFI8(K2, 5u)
    #pragma unroll
    for (int j = 0; j < 8; ++j) out[j] = a[j] ^ b[j];
}

// ---------------------------------------------------------------------------
__device__ __forceinline__ uint32_t smem_u32(const void* p) {
    uint32_t a;
    asm("{ .reg .u64 t; cvta.to.shared.u64 t, %1; cvt.u32.u64 %0, t; }" : "=r"(a) : "l"(p));
    return a;
}
__device__ __forceinline__ void cpa16(uint32_t dst, const void* src) {
    asm volatile("cp.async.cg.shared.global [%0], [%1], 16;" :: "r"(dst), "l"(src) : "memory");
}
__device__ __forceinline__ void cpa_commit() {
    asm volatile("cp.async.commit_group;" ::: "memory");
}
__device__ __forceinline__ void cpa_wait0() {
    asm volatile("cp.async.wait_group 0;" ::: "memory");
}
__device__ __forceinline__ void ldsm4(uint32_t* r, uint32_t addr) {
    asm volatile("ldmatrix.sync.aligned.m8n8.x4.shared.b16 {%0,%1,%2,%3}, [%4];"
                 : "=r"(r[0]), "=r"(r[1]), "=r"(r[2]), "=r"(r[3]) : "r"(addr));
}
__device__ __forceinline__ void ldsm4t(uint32_t* r, uint32_t addr) {
    asm volatile("ldmatrix.sync.aligned.m8n8.x4.trans.shared.b16 {%0,%1,%2,%3}, [%4];"
                 : "=r"(r[0]), "=r"(r[1]), "=r"(r[2]), "=r"(r[3]) : "r"(addr));
}
__device__ __forceinline__ void mma16816(float* d, const uint32_t* a, uint32_t b0, uint32_t b1) {
    asm volatile("mma.sync.aligned.m16n8k16.row.col.f32.bf16.bf16.f32 "
                 "{%0,%1,%2,%3}, {%4,%5,%6,%7}, {%8,%9}, {%0,%1,%2,%3};"
                 : "+f"(d[0]), "+f"(d[1]), "+f"(d[2]), "+f"(d[3])
                 : "r"(a[0]), "r"(a[1]), "r"(a[2]), "r"(a[3]), "r"(b0), "r"(b1));
}
__device__ __forceinline__ float ex2f(float x) {
    float r; asm("ex2.approx.f32 %0, %1;" : "=f"(r) : "f"(x)); return r;
}
__device__ __forceinline__ void split2f(float x, float y, uint32_t& hi, uint32_t& lo) {
    uint32_t h;
    asm("cvt.rn.bf16x2.f32 %0, %1, %2;" : "=r"(h) : "f"(y), "f"(x));
    float fx = __uint_as_float(h << 16);
    float fy = __uint_as_float(h & 0xffff0000u);
    uint32_t l;
    asm("cvt.rn.bf16x2.f32 %0, %1, %2;" : "=r"(l) : "f"(y - fy), "f"(x - fx));
    hi = h; lo = l;
}

// ============================================================================
// Kernel 1: split Q/K/V into bf16 hi/lo (Q pre-scaled)
// ============================================================================
__global__ __launch_bounds__(256)
void split_kernel(const float* __restrict__ Q,
                  const float* __restrict__ K,
                  const float* __restrict__ V) {
    using namespace cfg;
    const int i0 = blockIdx.x * 256 + threadIdx.x;
    #pragma unroll
    for (int r = 0; r < 2; ++r) {
        int i = i0 + r * 262144;
        float4 v = ((const float4*)Q)[i];
        v.x *= SCALE; v.y *= SCALE; v.z *= SCALE; v.w *= SCALE;
        uint32_t h0, l0, h1, l1;
        split2f(v.x, v.y, h0, l0); split2f(v.z, v.w, h1, l1);
        ((uint2*)g_Qhi)[i] = make_uint2(h0, h1);
        ((uint2*)g_Qlo)[i] = make_uint2(l0, l1);

        v = ((const float4*)K)[i];
        split2f(v.x, v.y, h0, l0); split2f(v.z, v.w, h1, l1);
        ((uint2*)g_Khi)[i] = make_uint2(h0, h1);
        ((uint2*)g_Klo)[i] = make_uint2(l0, l1);

        v = ((const float4*)V)[i];
        split2f(v.x, v.y, h0, l0); split2f(v.z, v.w, h1, l1);
        ((uint2*)g_Vhi)[i] = make_uint2(h0, h1);
        ((uint2*)g_Vlo)[i] = make_uint2(l0, l1);
    }
}

// ============================================================================
// Kernel 2: PERSISTENT mask kernel — 128 CTAs x 256 threads.
//   CTA k owns column c=k (c = bb*32+qt) and produces (c, it) for it=0..63
//   in order. One keep-word per thread per item; word content/index
//   bit-identical to round 10.
// ============================================================================
__global__ __launch_bounds__(256)
void mask_kernel() {
    using namespace cfg;
    const int tid  = threadIdx.x;
    const int c    = blockIdx.x;          // 0..127
    const int bb   = c >> 5, qt = c & 31;
    const int wd   = tid >> 5, lane = tid & 31;

    const int qrow = qt * BQ + wd * 16 + (lane >> 2);
    const uint32_t mrow0 = ((uint32_t)bb << 24) | ((uint32_t)qrow << 12);
    const uint32_t mrow1 = mrow0 + (8u << 12);

    for (int it = 0; it < NIT; ++it) {
        const int vb = it * BK;
        uint32_t keep = 0u;
        #pragma unroll
        for (int ks = 0; ks < 4; ++ks) {
            uint32_t ctr[8], bits[8];
            #pragma unroll
            for (int h2 = 0; h2 < 2; ++h2) {
                uint32_t cc = (uint32_t)(vb + (2 * ks + h2) * 8 + (lane & 3) * 2);
                ctr[h2 * 4 + 0] = mrow0 + cc;
                ctr[h2 * 4 + 1] = mrow0 + cc + 1u;
                ctr[h2 * 4 + 2] = mrow1 + cc;
                ctr[h2 * 4 + 3] = mrow1 + cc + 1u;
            }
            tf8(ctr, bits);
            #pragma unroll
            for (int u = 0; u < 8; ++u)
                if (bits[u] < KEEP) keep |= 1u << (ks * 8 + u);
        }
        g_mask[(uint32_t)(c * 64 + it) * 256u + (uint32_t)tid] = keep;
        __syncthreads();
        if (tid == 0) {
            __threadfence();
            atomicExch(&g_flags[c * 64 + it], 1u);
        }
    }
}

// ============================================================================
// Kernel 3: flash attention (HMMA); spins on the per-iter mask flag.
// ============================================================================
__global__ __launch_bounds__(cfg::THREADS, 1)
void attn_hmma_kernel(float* __restrict__ Og) {
    using namespace cfg;
    extern __shared__ char smem[];
    const uint32_t sb = smem_u32(smem);

    const int tid  = threadIdx.x;
    const int wid  = tid >> 5;
    const int lane = tid & 31;
    const int qt   = blockIdx.x;
    const int qblk = qt * BQ;
    const int bb   = blockIdx.y;
    const int cidx = bb * 32 + qt;

    const size_t tbase = (size_t)bb * SEQ * H;

    // ---- prologue: cp.async Q tile (hi+lo) and K/V tile 0 ----
    {
        const char* qh = (const char*)g_Qhi + (tbase + (size_t)qblk * H) * 2;
        const char* ql = (const char*)g_Qlo + (tbase + (size_t)qblk * H) * 2;
        #pragma unroll
        for (int i = 0; i < 8; ++i) {
            int idx = tid + i * 256;
            int row = idx >> 4, c = idx & 15;
            cpa16(sb + SM_QHI + row * RS + c * 16, qh + row * 256 + c * 16);
            cpa16(sb + SM_QLO + row * RS + c * 16, ql + row * 256 + c * 16);
        }
        const char* kh = (const char*)g_Khi + tbase * 2;
        const char* kl = (const char*)g_Klo + tbase * 2;
        const char* vh = (const char*)g_Vhi + tbase * 2;
        const char* vl = (const char*)g_Vlo + tbase * 2;
        #pragma unroll
        for (int j = 0; j < 4; ++j) {
            int idx = tid + j * 256;
            int row = idx >> 4, c = idx & 15;
            uint32_t d = sb + SM_BUF0 + row * RS + c * 16;
            int      s = row * 256 + c * 16;
            cpa16(d,             kh + s);
            cpa16(d + KTILE,     kl + s);
            cpa16(d + 2 * KTILE, vh + s);
            cpa16(d + 3 * KTILE, vl + s);
        }
        cpa_commit();
        cpa_wait0();
    }
    __syncthreads();

    const uint32_t abase   = sb + SM_QHI + (wid * 16 + (lane & 15)) * RS + (lane >> 4) * 16;
    const uint32_t kb_lane = (lane & 15) * RS + (lane >> 4) * 16;

    float o[16][4];
    #pragma unroll
    for (int j = 0; j < 16; ++j)
        #pragma unroll
        for (int c = 0; c < 4; ++c) o[j][c] = 0.0f;
    float m0 = -1e30f, m1 = -1e30f, l0 = 0.0f, l1 = 0.0f;

    for (int it = 0; it < NIT; ++it) {
        // ---- cp.async K/V tile it+1 into the other buffer ----
        if (it + 1 < NIT) {
            const size_t vb2 = (size_t)(it + 1) * BK;
            uint32_t bufn = sb + SM_BUF0 + (uint32_t)(((it + 1) & 1) * BUFSZ);
            const char* kh = (const char*)g_Khi + (tbase + vb2 * H) * 2;
            const char* kl = (const char*)g_Klo + (tbase + vb2 * H) * 2;
            const char* vh = (const char*)g_Vhi + (tbase + vb2 * H) * 2;
            const char* vl = (const char*)g_Vlo + (tbase + vb2 * H) * 2;
            #pragma unroll
            for (int j = 0; j < 4; ++j) {
                int idx = tid + j * 256;
                int row = idx >> 4, c = idx & 15;
                uint32_t d = bufn + row * RS + c * 16;
                int      s = row * 256 + c * 16;
                cpa16(d,             kh + s);
                cpa16(d + KTILE,     kl + s);
                cpa16(d + 2 * KTILE, vh + s);
                cpa16(d + 3 * KTILE, vl + s);
            }
            cpa_commit();
        }

        const uint32_t bufc = sb + SM_BUF0 + (uint32_t)((it & 1) * BUFSZ);
        const uint32_t bK = bufc + kb_lane;
        const uint32_t bV = bufc + 2 * KTILE + kb_lane;

        // ---- S = Qh*Kh + Qh*Kl + Ql*Kh ----
        float s[8][4];
        #pragma unroll
        for (int j = 0; j < 8; ++j)
            #pragma unroll
            for (int c = 0; c < 4; ++c) s[j][c] = 0.0f;

        #pragma unroll
        for (int ks = 0; ks < 8; ++ks) {
            uint32_t ah[4], al[4];
            ldsm4(ah, abase + ks * 32);
            ldsm4(al, abase + QTILE + ks * 32);
            #pragma unroll
            for (int np = 0; np < 2; ++np) {
                uint32_t bh0[4], bl0[4], bh1[4], bl1[4];
                ldsm4(bh0, bK + (2 * np) * (16 * RS) + ks * 32);
                ldsm4(bl0, bK + KTILE + (2 * np) * (16 * RS) + ks * 32);
                ldsm4(bh1, bK + (2 * np + 1) * (16 * RS) + ks * 32);
                ldsm4(bl1, bK + KTILE + (2 * np + 1) * (16 * RS) + ks * 32);
                float* s0 = s[4 * np];     float* s1 = s[4 * np + 1];
                float* s2 = s[4 * np + 2]; float* s3 = s[4 * np + 3];
                mma16816(s0, ah, bh0[0], bh0[2]);
                mma16816(s1, ah, bh0[1], bh0[3]);
                mma16816(s2, ah, bh1[0], bh1[2]);
                mma16816(s3, ah, bh1[1], bh1[3]);
                mma16816(s0, ah, bl0[0], bl0[2]);
                mma16816(s1, ah, bl0[1], bl0[3]);
                mma16816(s2, ah, bl1[0], bl1[2]);
                mma16816(s3, ah, bl1[1], bl1[3]);
                mma16816(s0, al, bh0[0], bh0[2]);
                mma16816(s1, al, bh0[1], bh0[3]);
                mma16816(s2, al, bh1[0], bh1[2]);
                mma16816(s3, al, bh1[1], bh1[3]);
            }
        }

        // ---- flag wait + keep-word load BEFORE softmax: L2 latency hides
        //      under the exp/shuffle block below ----
        uint32_t keep;
        {
            uint32_t f;
            const uint32_t* fp = &g_flags[cidx * 64 + it];
            do {
                asm volatile("ld.global.acquire.gpu.b32 %0, [%1];" : "=r"(f) : "l"(fp));
                if (!f) __nanosleep(128);
            } while (!f);
            keep = g_mask[(uint32_t)(cidx * 64 + it) * 256u + (uint32_t)tid];
        }

        // ---- online softmax (log2 units) ----
        float mx0 = -1e30f, mx1 = -1e30f;
        #pragma unroll
        for (int j = 0; j < 8; ++j) {
            mx0 = fmaxf(mx0, fmaxf(s[j][0], s[j][1]));
            mx1 = fmaxf(mx1, fmaxf(s[j][2], s[j][3]));
        }
        #pragma unroll
        for (int off = 1; off < 4; off <<= 1) {
            mx0 = fmaxf(mx0, __shfl_xor_sync(0xffffffffu, mx0, off));
            mx1 = fmaxf(mx1, __shfl_xor_sync(0xffffffffu, mx1, off));
        }
        float mn0 = fmaxf(m0, mx0), mn1 = fmaxf(m1, mx1);
        float al0 = ex2f(m0 - mn0), al1 = ex2f(m1 - mn1);
        m0 = mn0; m1 = mn1;

        float ls0 = 0.0f, ls1 = 0.0f;
        #pragma unroll
        for (int j = 0; j < 8; ++j) {
            s[j][0] = ex2f(s[j][0] - mn0); ls0 += s[j][0];
            s[j][1] = ex2f(s[j][1] - mn0); ls0 += s[j][1];
            s[j][2] = ex2f(s[j][2] - mn1); ls1 += s[j][2];
            s[j][3] = ex2f(s[j][3] - mn1); ls1 += s[j][3];
        }
        #pragma unroll
        for (int off = 1; off < 4; off <<= 1) {
            ls0 += __shfl_xor_sync(0xffffffffu, ls0, off);
            ls1 += __shfl_xor_sync(0xffffffffu, ls1, off);
        }
        l0 = l0 * al0 + ls0;
        l1 = l1 * al1 + ls1;

        #pragma unroll
        for (int j = 0; j < 16; ++j) {
            o[j][0] *= al0; o[j][1] *= al0;
            o[j][2] *= al1; o[j][3] *= al1;
        }

        // ---- apply keep bits + build P hi/lo fragments + PV MMAs ----
        #pragma unroll
        for (int ks = 0; ks < 4; ++ks) {
            uint32_t phi4[4], plo4[4];
            #pragma unroll
            for (int h2 = 0; h2 < 2; ++h2) {
                int j = 2 * ks + h2;
                uint32_t kb = keep >> (ks * 8 + h2 * 4);
                float p0 = (kb & 1u) ? s[j][0] : 0.0f;
                float p1 = (kb & 2u) ? s[j][1] : 0.0f;
                float p2 = (kb & 4u) ? s[j][2] : 0.0f;
                float p3 = (kb & 8u) ? s[j][3] : 0.0f;
                split2f(p0, p1, phi4[h2 * 2],     plo4[h2 * 2]);
                split2f(p2, p3, phi4[h2 * 2 + 1], plo4[h2 * 2 + 1]);
            }
            #pragma unroll
            for (int hp = 0; hp < 4; ++hp) {
                uint32_t bh0[4], bl0[4], bh1[4], bl1[4];
                ldsm4t(bh0, bV + ks * (16 * RS) + (2 * hp) * 32);
                ldsm4t(bl0, bV + KTILE + ks * (16 * RS) + (2 * hp) * 32);
                ldsm4t(bh1, bV + ks * (16 * RS) + (2 * hp + 1) * 32);
                ldsm4t(bl1, bV + KTILE + ks * (16 * RS) + (2 * hp + 1) * 32);
                float* o0 = o[4 * hp];     float* o1 = o[4 * hp + 1];
                float* o2 = o[4 * hp + 2]; float* o3 = o[4 * hp + 3];
                mma16816(o0, phi4, bh0[0], bh0[1]);
                mma16816(o1, phi4, bh0[2], bh0[3]);
                mma16816(o2, phi4, bh1[0], bh1[1]);
                mma16816(o3, phi4, bh1[2], bh1[3]);
                mma16816(o0, phi4, bl0[0], bl0[1]);
                mma16816(o1, phi4, bl0[2], bl0[3]);
                mma16816(o2, phi4, bl1[0], bl1[1]);
                mma16816(o3, phi4, bl1[2], bl1[3]);
                mma16816(o0, plo4, bh0[0], bh0[1]);
                mma16816(o1, plo4, bh0[2], bh0[3]);
                mma16816(o2, plo4, bh1[0], bh1[1]);
                mma16816(o3, plo4, bh1[2], bh1[3]);
            }
        }

        cpa_wait0();
        __syncthreads();
    }

    // ---- epilogue: O /= (0.9 * l) ----
    const int row_g0 = qblk + wid * 16 + (lane >> 2);
    float inv0 = 1.0f / (0.9f * l0);
    float inv1 = 1.0f / (0.9f * l1);
    float* out0 = Og + ((size_t)bb * SEQ + row_g0) * H;
    float* out1 = out0 + 8 * H;
    #pragma unroll
    for (int j = 0; j < 16; ++j) {
        int h = j * 8 + (lane & 3) * 2;
        *(float2*)(out0 + h) = make_float2(o[j][0] * inv0, o[j][1] * inv0);
        *(float2*)(out1 + h) = make_float2(o[j][2] * inv1, o[j][3] * inv1);
    }
}

// ============================================================================
extern "C" void kernel_launch(void* const* d_in, const int* in_sizes, int n_in,
                              void* d_out, int out_size) {
    const float* Q = (const float*)d_in[0];
    const float* K = (const float*)d_in[1];
    const float* V = (const float*)d_in[2];
    float* O = (float*)d_out;
    (void)in_sizes; (void)n_in; (void)out_size;

    static cudaStream_t s2 = nullptr;
    static cudaEvent_t evF = nullptr, evJ = nullptr;
    if (s2 == nullptr) {
        cudaStreamCreateWithFlags(&s2, cudaStreamNonBlocking);
        cudaEventCreateWithFlags(&evF, cudaEventDisableTiming);
        cudaEventCreateWithFlags(&evJ, cudaEventDisableTiming);
        cudaFuncSetAttribute(attn_hmma_kernel,
                             cudaFuncAttributeMaxDynamicSharedMemorySize,
                             cfg::SMEM_TOTAL);
    }

    // fork: non-floodable (grid==128) persistent mask kernel beside split->attn
    cudaEventRecord(evF, 0);
    cudaStreamWaitEvent(s2, evF, 0);
    mask_kernel<<<cfg::MASK_CTAS, 256, 0, s2>>>();

    split_kernel<<<1024, 256>>>(Q, K, V);
    dim3 grid(cfg::SEQ / cfg::BQ, 4);
    attn_hmma_kernel<<<grid, cfg::THREADS, cfg::SMEM_TOTAL>>>(O);

    // join
    cudaEventRecord(evJ, s2);
    cudaStreamWaitEvent(0, evJ, 0);
}

// round 15
// speedup vs baseline: 2.0727x; 1.6562x over previous
#include <cuda_runtime.h>
#include <cuda_bf16.h>
#include <cstdint>

// ============================================================================
// Fused flash attention (HMMA, base sm_103 target), 2 serial kernels:
//   K1 split: Q(scaled)/K/V -> bf16 hi/lo device globals (once).
//   K2 attn:  flash kernel with LAZY dropout — logits have sigma~185 (log2),
//       softmax rows are near-one-hot, so only entries with p > 2^-30 can
//       observably be masked. keep defaults to 1; the bit-exact threefry
//       (JAX partitionable, key (0,42), bits=o1^o2, keep <=> bits<7549747*512,
//       verified round 2) is computed only for those rare entries
//       (~0.25 per warp-iteration). Sub-threshold entries contribute
//       <= 4096*2^-30 ~ 4e-6 relative — far under the 1e-3 threshold.
// ============================================================================

namespace cfg {
constexpr int H = 128, SEQ = 4096, BQ = 128, BK = 64;
constexpr int NIT = SEQ / BK;                      // 64
constexpr int THREADS = 256;
constexpr uint32_t KEEP = 3865470464u;
constexpr float SCALE = 11.313708498984760390f * 1.4426950408889634074f; // sqrt(128)*log2e
constexpr int RS     = 272;
constexpr int QTILE  = BQ * RS;                    // 34816
constexpr int KTILE  = BK * RS;                    // 17408
constexpr int SM_QHI = 0;
constexpr int SM_QLO = QTILE;
constexpr int SM_BUF0 = 2 * QTILE;
constexpr int BUFSZ  = 4 * KTILE;                  // KHI|KLO|VHI|VLO
constexpr int SMEM_TOTAL = SM_BUF0 + 2 * BUFSZ;    // 208896 B
constexpr float SIG_TH = 9.313225746154785e-10f;   // 2^-30
}

// ---- device globals: pre-split operands -----------------------------------
__device__ __align__(16) uint32_t g_Qhi[1048576];
__device__ __align__(16) uint32_t g_Qlo[1048576];
__device__ __align__(16) uint32_t g_Khi[1048576];
__device__ __align__(16) uint32_t g_Klo[1048576];
__device__ __align__(16) uint32_t g_Vhi[1048576];
__device__ __align__(16) uint32_t g_Vlo[1048576];

// ---------------------------------------------------------------------------
// threefry-2x32-20, key (0,42), ctr (0,m) -> o1 ^ o2  (bit-exact, round 2)
#define TF_ROUND(a, b, r) { (a) += (b); (b) = __funnelshift_l((b), (b), (r)); (b) ^= (a); }
__device__ __forceinline__ uint32_t tf_bits(uint32_t b) {
    const uint32_t K1 = 42u, K2 = 0x1BD11BF0u;
    uint32_t a = 0u;
    b += K1;
    TF_ROUND(a,b,13) TF_ROUND(a,b,15) TF_ROUND(a,b,26) TF_ROUND(a,b,6)
    a += K1; b += K2 + 1u;
    TF_ROUND(a,b,17) TF_ROUND(a,b,29) TF_ROUND(a,b,16) TF_ROUND(a,b,24)
    a += K2; b += 2u;
    TF_ROUND(a,b,13) TF_ROUND(a,b,15) TF_ROUND(a,b,26) TF_ROUND(a,b,6)
    b += K1 + 3u;
    TF_ROUND(a,b,17) TF_ROUND(a,b,29) TF_ROUND(a,b,16) TF_ROUND(a,b,24)
    a += K1; b += K2 + 4u;
    TF_ROUND(a,b,13) TF_ROUND(a,b,15) TF_ROUND(a,b,26) TF_ROUND(a,b,6)
    a += K2; b += 5u;
    return a ^ b;
}

// ---------------------------------------------------------------------------
__device__ __forceinline__ uint32_t smem_u32(const void* p) {
    uint32_t a;
    asm("{ .reg .u64 t; cvta.to.shared.u64 t, %1; cvt.u32.u64 %0, t; }" : "=r"(a) : "l"(p));
    return a;
}
__device__ __forceinline__ void cpa16(uint32_t dst, const void* src) {
    asm volatile("cp.async.cg.shared.global [%0], [%1], 16;" :: "r"(dst), "l"(src) : "memory");
}
__device__ __forceinline__ void cpa_commit() {
    asm volatile("cp.async.commit_group;" ::: "memory");
}
__device__ __forceinline__ void cpa_wait0() {
    asm volatile("cp.async.wait_group 0;" ::: "memory");
}
__device__ __forceinline__ void ldsm4(uint32_t* r, uint32_t addr) {
    asm volatile("ldmatrix.sync.aligned.m8n8.x4.shared.b16 {%0,%1,%2,%3}, [%4];"
                 : "=r"(r[0]), "=r"(r[1]), "=r"(r[2]), "=r"(r[3]) : "r"(addr));
}
__device__ __forceinline__ void ldsm4t(uint32_t* r, uint32_t addr) {
    asm volatile("ldmatrix.sync.aligned.m8n8.x4.trans.shared.b16 {%0,%1,%2,%3}, [%4];"
                 : "=r"(r[0]), "=r"(r[1]), "=r"(r[2]), "=r"(r[3]) : "r"(addr));
}
__device__ __forceinline__ void mma16816(float* d, const uint32_t* a, uint32_t b0, uint32_t b1) {
    asm volatile("mma.sync.aligned.m16n8k16.row.col.f32.bf16.bf16.f32 "
                 "{%0,%1,%2,%3}, {%4,%5,%6,%7}, {%8,%9}, {%0,%1,%2,%3};"
                 : "+f"(d[0]), "+f"(d[1]), "+f"(d[2]), "+f"(d[3])
                 : "r"(a[0]), "r"(a[1]), "r"(a[2]), "r"(a[3]), "r"(b0), "r"(b1));
}
__device__ __forceinline__ float ex2f(float x) {
    float r; asm("ex2.approx.f32 %0, %1;" : "=f"(r) : "f"(x)); return r;
}
__device__ __forceinline__ void split2f(float x, float y, uint32_t& hi, uint32_t& lo) {
    uint32_t h;
    asm("cvt.rn.bf16x2.f32 %0, %1, %2;" : "=r"(h) : "f"(y), "f"(x));
    float fx = __uint_as_float(h << 16);
    float fy = __uint_as_float(h & 0xffff0000u);
    uint32_t l;
    asm("cvt.rn.bf16x2.f32 %0, %1, %2;" : "=r"(l) : "f"(y - fy), "f"(x - fx));
    hi = h; lo = l;
}

// ============================================================================
// Kernel 1: split Q/K/V into bf16 hi/lo (Q pre-scaled)
// ============================================================================
__global__ __launch_bounds__(256)
void split_kernel(const float* __restrict__ Q,
                  const float* __restrict__ K,
                  const float* __restrict__ V) {
    using namespace cfg;
    const int i0 = blockIdx.x * 256 + threadIdx.x;
    #pragma unroll
    for (int r = 0; r < 2; ++r) {
        int i = i0 + r * 262144;
        float4 v = ((const float4*)Q)[i];
        v.x *= SCALE; v.y *= SCALE; v.z *= SCALE; v.w *= SCALE;
        uint32_t h0, l0, h1, l1;
        split2f(v.x, v.y, h0, l0); split2f(v.z, v.w, h1, l1);
        ((uint2*)g_Qhi)[i] = make_uint2(h0, h1);
        ((uint2*)g_Qlo)[i] = make_uint2(l0, l1);

        v = ((const float4*)K)[i];
        split2f(v.x, v.y, h0, l0); split2f(v.z, v.w, h1, l1);
        ((uint2*)g_Khi)[i] = make_uint2(h0, h1);
        ((uint2*)g_Klo)[i] = make_uint2(l0, l1);

        v = ((const float4*)V)[i];
        split2f(v.x, v.y, h0, l0); split2f(v.z, v.w, h1, l1);
        ((uint2*)g_Vhi)[i] = make_uint2(h0, h1);
        ((uint2*)g_Vlo)[i] = make_uint2(l0, l1);
    }
}

// ============================================================================
// Kernel 2: flash attention (HMMA) with lazy dropout
// ============================================================================
__global__ __launch_bounds__(cfg::THREADS, 1)
void attn_hmma_kernel(float* __restrict__ Og) {
    using namespace cfg;
    extern __shared__ char smem[];
    const uint32_t sb = smem_u32(smem);

    const int tid  = threadIdx.x;
    const int wid  = tid >> 5;
    const int lane = tid & 31;
    const int qt   = blockIdx.x;
    const int qblk = qt * BQ;
    const int bb   = blockIdx.y;

    const size_t tbase = (size_t)bb * SEQ * H;

    // ---- prologue: cp.async Q tile (hi+lo) and K/V tile 0 ----
    {
        const char* qh = (const char*)g_Qhi + (tbase + (size_t)qblk * H) * 2;
        const char* ql = (const char*)g_Qlo + (tbase + (size_t)qblk * H) * 2;
        #pragma unroll
        for (int i = 0; i < 8; ++i) {
            int idx = tid + i * 256;
            int row = idx >> 4, c = idx & 15;
            cpa16(sb + SM_QHI + row * RS + c * 16, qh + row * 256 + c * 16);
            cpa16(sb + SM_QLO + row * RS + c * 16, ql + row * 256 + c * 16);
        }
        const char* kh = (const char*)g_Khi + tbase * 2;
        const char* kl = (const char*)g_Klo + tbase * 2;
        const char* vh = (const char*)g_Vhi + tbase * 2;
        const char* vl = (const char*)g_Vlo + tbase * 2;
        #pragma unroll
        for (int j = 0; j < 4; ++j) {
            int idx = tid + j * 256;
            int row = idx >> 4, c = idx & 15;
            uint32_t d = sb + SM_BUF0 + row * RS + c * 16;
            int      s = row * 256 + c * 16;
            cpa16(d,             kh + s);
            cpa16(d + KTILE,     kl + s);
            cpa16(d + 2 * KTILE, vh + s);
            cpa16(d + 3 * KTILE, vl + s);
        }
        cpa_commit();
        cpa_wait0();
    }
    __syncthreads();

    const uint32_t abase   = sb + SM_QHI + (wid * 16 + (lane & 15)) * RS + (lane >> 4) * 16;
    const uint32_t kb_lane = (lane & 15) * RS + (lane >> 4) * 16;

    const int row_g0 = qblk + wid * 16 + (lane >> 2);
    const uint32_t mrow0 = ((uint32_t)bb << 24) | ((uint32_t)row_g0 << 12);
    const uint32_t mrow1 = mrow0 + (8u << 12);
    const uint32_t lane2 = (uint32_t)((lane & 3) * 2);

    float o[16][4];
    #pragma unroll
    for (int j = 0; j < 16; ++j)
        #pragma unroll
        for (int c = 0; c < 4; ++c) o[j][c] = 0.0f;
    float m0 = -1e30f, m1 = -1e30f, l0 = 0.0f, l1 = 0.0f;

    for (int it = 0; it < NIT; ++it) {
        const int vb = it * BK;

        // ---- cp.async K/V tile it+1 into the other buffer ----
        if (it + 1 < NIT) {
            const size_t vb2 = (size_t)(it + 1) * BK;
            uint32_t bufn = sb + SM_BUF0 + (uint32_t)(((it + 1) & 1) * BUFSZ);
            const char* kh = (const char*)g_Khi + (tbase + vb2 * H) * 2;
            const char* kl = (const char*)g_Klo + (tbase + vb2 * H) * 2;
            const char* vh = (const char*)g_Vhi + (tbase + vb2 * H) * 2;
            const char* vl = (const char*)g_Vlo + (tbase + vb2 * H) * 2;
            #pragma unroll
            for (int j = 0; j < 4; ++j) {
                int idx = tid + j * 256;
                int row = idx >> 4, c = idx & 15;
                uint32_t d = bufn + row * RS + c * 16;
                int      s = row * 256 + c * 16;
                cpa16(d,             kh + s);
                cpa16(d + KTILE,     kl + s);
                cpa16(d + 2 * KTILE, vh + s);
                cpa16(d + 3 * KTILE, vl + s);
            }
            cpa_commit();
        }

        const uint32_t bufc = sb + SM_BUF0 + (uint32_t)((it & 1) * BUFSZ);
        const uint32_t bK = bufc + kb_lane;
        const uint32_t bV = bufc + 2 * KTILE + kb_lane;

        // ---- S = Qh*Kh + Qh*Kl + Ql*Kh  (dep distance 4) ----
        float s[8][4];
        #pragma unroll
        for (int j = 0; j < 8; ++j)
            #pragma unroll
            for (int c = 0; c < 4; ++c) s[j][c] = 0.0f;

        #pragma unroll
        for (int ks = 0; ks < 8; ++ks) {
            uint32_t ah[4], al[4];
            ldsm4(ah, abase + ks * 32);
            ldsm4(al, abase + QTILE + ks * 32);
            #pragma unroll
            for (int np = 0; np < 2; ++np) {
                uint32_t bh0[4], bl0[4], bh1[4], bl1[4];
                ldsm4(bh0, bK + (2 * np) * (16 * RS) + ks * 32);
                ldsm4(bl0, bK + KTILE + (2 * np) * (16 * RS) + ks * 32);
                ldsm4(bh1, bK + (2 * np + 1) * (16 * RS) + ks * 32);
                ldsm4(bl1, bK + KTILE + (2 * np + 1) * (16 * RS) + ks * 32);
                float* s0 = s[4 * np];     float* s1 = s[4 * np + 1];
                float* s2 = s[4 * np + 2]; float* s3 = s[4 * np + 3];
                mma16816(s0, ah, bh0[0], bh0[2]);
                mma16816(s1, ah, bh0[1], bh0[3]);
                mma16816(s2, ah, bh1[0], bh1[2]);
                mma16816(s3, ah, bh1[1], bh1[3]);
                mma16816(s0, ah, bl0[0], bl0[2]);
                mma16816(s1, ah, bl0[1], bl0[3]);
                mma16816(s2, ah, bl1[0], bl1[2]);
                mma16816(s3, ah, bl1[1], bl1[3]);
                mma16816(s0, al, bh0[0], bh0[2]);
                mma16816(s1, al, bh0[1], bh0[3]);
                mma16816(s2, al, bh1[0], bh1[2]);
                mma16816(s3, al, bh1[1], bh1[3]);
            }
        }

        // ---- online softmax (log2 units), collect significance mask ----
        float mx0 = -1e30f, mx1 = -1e30f;
        #pragma unroll
        for (int j = 0; j < 8; ++j) {
            mx0 = fmaxf(mx0, fmaxf(s[j][0], s[j][1]));
            mx1 = fmaxf(mx1, fmaxf(s[j][2], s[j][3]));
        }
        #pragma unroll
        for (int off = 1; off < 4; off <<= 1) {
            mx0 = fmaxf(mx0, __shfl_xor_sync(0xffffffffu, mx0, off));
            mx1 = fmaxf(mx1, __shfl_xor_sync(0xffffffffu, mx1, off));
        }
        float mn0 = fmaxf(m0, mx0), mn1 = fmaxf(m1, mx1);
        float al0 = ex2f(m0 - mn0), al1 = ex2f(m1 - mn1);
        m0 = mn0; m1 = mn1;

        uint32_t sig = 0u;
        float ls0 = 0.0f, ls1 = 0.0f;
        #pragma unroll
        for (int j = 0; j < 8; ++j) {
            const int bb0 = (j >> 1) * 8 + (j & 1) * 4;  // keep-bit base for this tile
            s[j][0] = ex2f(s[j][0] - mn0); ls0 += s[j][0];
            s[j][1] = ex2f(s[j][1] - mn0); ls0 += s[j][1];
            s[j][2] = ex2f(s[j][2] - mn1); ls1 += s[j][2];
            s[j][3] = ex2f(s[j][3] - mn1); ls1 += s[j][3];
            if (s[j][0] > SIG_TH) sig |= 1u << bb0;
            if (s[j][1] > SIG_TH) sig |= 2u << bb0;
            if (s[j][2] > SIG_TH) sig |= 4u << bb0;
            if (s[j][3] > SIG_TH) sig |= 8u << bb0;
        }
        #pragma unroll
        for (int off = 1; off < 4; off <<= 1) {
            ls0 += __shfl_xor_sync(0xffffffffu, ls0, off);
            ls1 += __shfl_xor_sync(0xffffffffu, ls1, off);
        }
        l0 = l0 * al0 + ls0;
        l1 = l1 * al1 + ls1;

        #pragma unroll
        for (int j = 0; j < 16; ++j) {
            o[j][0] *= al0; o[j][1] *= al0;
            o[j][2] *= al1; o[j][3] *= al1;
        }

        // ---- LAZY dropout: exact threefry only for significant entries ----
        uint32_t keep = 0xFFFFFFFFu;
        if (__ballot_sync(0xffffffffu, sig != 0u)) {
            uint32_t ss = sig;
            while (ss) {
                int b = __ffs(ss) - 1; ss &= ss - 1u;
                int j = 2 * (b >> 3) + ((b >> 2) & 1);
                int e = b & 3;
                uint32_t ctr = ((e & 2) ? mrow1 : mrow0)
                             + (uint32_t)(vb + j * 8) + lane2 + (uint32_t)(e & 1);
                if (tf_bits(ctr) >= KEEP) keep &= ~(1u << b);
            }
        }

        // ---- apply keep bits + build P hi/lo fragments + PV MMAs ----
        #pragma unroll
        for (int ks = 0; ks < 4; ++ks) {
            uint32_t phi4[4], plo4[4];
            #pragma unroll
            for (int h2 = 0; h2 < 2; ++h2) {
                int j = 2 * ks + h2;
                uint32_t kb = keep >> (ks * 8 + h2 * 4);
                float p0 = (kb & 1u) ? s[j][0] : 0.0f;
                float p1 = (kb & 2u) ? s[j][1] : 0.0f;
                float p2 = (kb & 4u) ? s[j][2] : 0.0f;
                float p3 = (kb & 8u) ? s[j][3] : 0.0f;
                split2f(p0, p1, phi4[h2 * 2],     plo4[h2 * 2]);
                split2f(p2, p3, phi4[h2 * 2 + 1], plo4[h2 * 2 + 1]);
            }
            #pragma unroll
            for (int hp = 0; hp < 4; ++hp) {
                uint32_t bh0[4], bl0[4], bh1[4], bl1[4];
                ldsm4t(bh0, bV + ks * (16 * RS) + (2 * hp) * 32);
                ldsm4t(bl0, bV + KTILE + ks * (16 * RS) + (2 * hp) * 32);
                ldsm4t(bh1, bV + ks * (16 * RS) + (2 * hp + 1) * 32);
                ldsm4t(bl1, bV + KTILE + ks * (16 * RS) + (2 * hp + 1) * 32);
                float* o0 = o[4 * hp];     float* o1 = o[4 * hp + 1];
                float* o2 = o[4 * hp + 2]; float* o3 = o[4 * hp + 3];
                mma16816(o0, phi4, bh0[0], bh0[1]);
                mma16816(o1, phi4, bh0[2], bh0[3]);
                mma16816(o2, phi4, bh1[0], bh1[1]);
                mma16816(o3, phi4, bh1[2], bh1[3]);
                mma16816(o0, phi4, bl0[0], bl0[1]);
                mma16816(o1, phi4, bl0[2], bl0[3]);
                mma16816(o2, phi4, bl1[0], bl1[1]);
                mma16816(o3, phi4, bl1[2], bl1[3]);
                mma16816(o0, plo4, bh0[0], bh0[1]);
                mma16816(o1, plo4, bh0[2], bh0[3]);
                mma16816(o2, plo4, bh1[0], bh1[1]);
                mma16816(o3, plo4, bh1[2], bh1[3]);
            }
        }

        cpa_wait0();
        __syncthreads();
    }

    // ---- epilogue: O /= (0.9 * l) ----
    float inv0 = 1.0f / (0.9f * l0);
    float inv1 = 1.0f / (0.9f * l1);
    float* out0 = Og + ((size_t)bb * SEQ + row_g0) * H;
    float* out1 = out0 + 8 * H;
    #pragma unroll
    for (int j = 0; j < 16; ++j) {
        int h = j * 8 + (lane & 3) * 2;
        *(float2*)(out0 + h) = make_float2(o[j][0] * inv0, o[j][1] * inv0);
        *(float2*)(out1 + h) = make_float2(o[j][2] * inv1, o[j][3] * inv1);
    }
}

// ============================================================================
extern "C" void kernel_launch(void* const* d_in, const int* in_sizes, int n_in,
                              void* d_out, int out_size) {
    const float* Q = (const float*)d_in[0];
    const float* K = (const float*)d_in[1];
    const float* V = (const float*)d_in[2];
    float* O = (float*)d_out;
    (void)in_sizes; (void)n_in; (void)out_size;

    split_kernel<<<1024, 256>>>(Q, K, V);

    cudaFuncSetAttribute(attn_hmma_kernel,
                         cudaFuncAttributeMaxDynamicSharedMemorySize, cfg::SMEM_TOTAL);
    dim3 grid(cfg::SEQ / cfg::BQ, 4);
    attn_hmma_kernel<<<grid, cfg::THREADS, cfg::SMEM_TOTAL>>>(O);
}